// round 1
// baseline (speedup 1.0000x reference)
#include <cuda_runtime.h>
#include <cstdint>
#include <math.h>

#define BATCH 4
#define SEQ 2048
#define DMODEL 1024
#define NHEADS 16
#define DHEAD 64
#define MTOT (BATCH*SEQ)   // 8192

// ---------------- scratch (device globals: allocation-free) ----------------
__device__ float g_Qh[(size_t)BATCH*NHEADS*SEQ*DHEAD]; // [B,H,L,Dh]
__device__ float g_Kh[(size_t)BATCH*NHEADS*SEQ*DHEAD];
__device__ float g_Vh[(size_t)BATCH*NHEADS*SEQ*DHEAD];
__device__ float g_O [(size_t)BATCH*SEQ*DMODEL];       // [B,L,D] attention out

// ---------------- tf32 helpers ----------------
__device__ __forceinline__ uint32_t f2tf(float x){
    uint32_t r; asm("cvt.rna.tf32.f32 %0, %1;" : "=r"(r) : "f"(x)); return r;
}
__device__ __forceinline__ void mma8(float* c, const uint32_t* a, const uint32_t* b){
    asm volatile("mma.sync.aligned.m16n8k8.row.col.f32.tf32.tf32.f32 "
        "{%0,%1,%2,%3}, {%4,%5,%6,%7}, {%8,%9}, {%0,%1,%2,%3};"
        : "+f"(c[0]), "+f"(c[1]), "+f"(c[2]), "+f"(c[3])
        : "r"(a[0]), "r"(a[1]), "r"(a[2]), "r"(a[3]), "r"(b[0]), "r"(b[1]));
}

// ============================================================================
// GEMM: C[M=8192, N=1024] = A[M,K=1024] @ W[K,N] + bias
// Block 128x128, 256 threads (8 warps, 4x2), warp tile 32x64, k-tile 32.
// outMode: 0 -> flat to outflat; 1/2/3 -> head-split layout into g_Qh/g_Kh/g_Vh
// Ain == nullptr -> read A from g_O.
// ============================================================================
__global__ __launch_bounds__(256) void gemm_tf32(
    const float* __restrict__ Ain, const float* __restrict__ W,
    const float* __restrict__ bias, float* __restrict__ outflat, int outMode)
{
    const float* A = Ain ? Ain : g_O;
    __shared__ float As[32][133];  // [k][m]
    __shared__ float Bs[32][132];  // [k][n]

    const int tid = threadIdx.x;
    const int warpId = tid >> 5, lane = tid & 31;
    const int groupId = lane >> 2, tig = lane & 3;
    const int wm = warpId & 3;        // 4 warps along M (32 rows each)
    const int wn = warpId >> 2;       // 2 warps along N (64 cols each)
    const int m0 = blockIdx.y * 128;
    const int n0 = blockIdx.x * 128;

    float acc[2][8][4];
    #pragma unroll
    for (int mt = 0; mt < 2; mt++)
        #pragma unroll
        for (int nt = 0; nt < 8; nt++)
            #pragma unroll
            for (int e = 0; e < 4; e++) acc[mt][nt][e] = 0.f;

    const int ka = tid & 31, ma = tid >> 5;     // A-load coords
    const int nb = tid & 127, kb = tid >> 7;    // B-load coords

    for (int kt = 0; kt < DMODEL; kt += 32) {
        #pragma unroll
        for (int p = 0; p < 16; p++) {
            int m = ma + p * 8;
            As[ka][m] = A[(size_t)(m0 + m) * DMODEL + kt + ka];
        }
        #pragma unroll
        for (int p = 0; p < 16; p++) {
            int k = kb + p * 2;
            Bs[k][nb] = W[(size_t)(kt + k) * DMODEL + n0 + nb];
        }
        __syncthreads();

        #pragma unroll
        for (int kk = 0; kk < 32; kk += 8) {
            uint32_t af[2][4], bf[8][2];
            #pragma unroll
            for (int mt = 0; mt < 2; mt++) {
                int mr = wm * 32 + mt * 16 + groupId;
                af[mt][0] = f2tf(As[kk + tig    ][mr    ]);
                af[mt][1] = f2tf(As[kk + tig    ][mr + 8]);
                af[mt][2] = f2tf(As[kk + tig + 4][mr    ]);
                af[mt][3] = f2tf(As[kk + tig + 4][mr + 8]);
            }
            #pragma unroll
            for (int nt = 0; nt < 8; nt++) {
                int nc = wn * 64 + nt * 8 + groupId;
                bf[nt][0] = f2tf(Bs[kk + tig    ][nc]);
                bf[nt][1] = f2tf(Bs[kk + tig + 4][nc]);
            }
            #pragma unroll
            for (int mt = 0; mt < 2; mt++)
                #pragma unroll
                for (int nt = 0; nt < 8; nt++)
                    mma8(acc[mt][nt], af[mt], bf[nt]);
        }
        __syncthreads();
    }

    // epilogue
    float* splitDst = (outMode == 1) ? g_Qh : (outMode == 2) ? g_Kh : g_Vh;
    #pragma unroll
    for (int mt = 0; mt < 2; mt++) {
        #pragma unroll
        for (int nt = 0; nt < 8; nt++) {
            int r0 = m0 + wm * 32 + mt * 16 + groupId;
            int c0 = n0 + wn * 64 + nt * 8 + tig * 2;
            #pragma unroll
            for (int e = 0; e < 4; e++) {
                int r = r0 + ((e >= 2) ? 8 : 0);
                int c = c0 + (e & 1);
                float v = acc[mt][nt][e] + bias[c];
                if (outMode == 0) {
                    outflat[(size_t)r * DMODEL + c] = v;
                } else {
                    int b = r >> 11, l = r & (SEQ - 1);
                    int h = c >> 6, d = c & (DHEAD - 1);
                    splitDst[((((size_t)b * NHEADS + h) * SEQ) + l) * DHEAD + d] = v;
                }
            }
        }
    }
}

// ============================================================================
// Flash attention (causal). Grid: (L/64, B*H). 128 threads = 4 warps.
// Each block: 64 query rows x Dh=64. Online softmax, tf32 mma for QK^T and PV.
// Writes directly to g_O in [B, L, D] layout.
// ============================================================================
__global__ __launch_bounds__(128) void attn_kernel()
{
    __shared__ float Ks[64][68];   // K tile; reused as P tile; also Q staging
    __shared__ float Vs[64][68];   // V tile

    const int tid = threadIdx.x;
    const int warp = tid >> 5, lane = tid & 31;
    const int groupId = lane >> 2, tig = lane & 3;
    const int bh = blockIdx.y;
    const int qt = blockIdx.x;
    const int q0 = qt * 64;

    const float* Qp = g_Qh + (size_t)bh * SEQ * DHEAD;
    const float* Kp = g_Kh + (size_t)bh * SEQ * DHEAD;
    const float* Vp = g_Vh + (size_t)bh * SEQ * DHEAD;

    const int lrow = tid >> 6;     // 0..1
    const int lcol = tid & 63;     // 0..63

    // ---- stage Q tile (scaled by 1/sqrt(Dh)) into Ks, then lift to registers
    #pragma unroll
    for (int p = 0; p < 32; p++) {
        int r = lrow + p * 2;
        Ks[r][lcol] = Qp[(size_t)(q0 + r) * DHEAD + lcol] * 0.125f;
    }
    __syncthreads();

    uint32_t qf[8][4];
    #pragma unroll
    for (int kk = 0; kk < 8; kk++) {
        int mr = warp * 16 + groupId;
        qf[kk][0] = f2tf(Ks[mr    ][kk * 8 + tig    ]);
        qf[kk][1] = f2tf(Ks[mr + 8][kk * 8 + tig    ]);
        qf[kk][2] = f2tf(Ks[mr    ][kk * 8 + tig + 4]);
        qf[kk][3] = f2tf(Ks[mr + 8][kk * 8 + tig + 4]);
    }
    __syncthreads();

    float oacc[8][4];
    #pragma unroll
    for (int nt = 0; nt < 8; nt++)
        #pragma unroll
        for (int e = 0; e < 4; e++) oacc[nt][e] = 0.f;
    float mrun[2] = {-INFINITY, -INFINITY};
    float lrun[2] = {0.f, 0.f};

    for (int j = 0; j <= qt; j++) {
        // load K, V tiles (row = key index, col = d)
        #pragma unroll
        for (int p = 0; p < 32; p++) {
            int r = lrow + p * 2;
            Ks[r][lcol] = Kp[(size_t)(j * 64 + r) * DHEAD + lcol];
            Vs[r][lcol] = Vp[(size_t)(j * 64 + r) * DHEAD + lcol];
        }
        __syncthreads();

        // S = Q K^T  (scaled Q already)
        float s[8][4];
        #pragma unroll
        for (int nt = 0; nt < 8; nt++)
            #pragma unroll
            for (int e = 0; e < 4; e++) s[nt][e] = 0.f;

        #pragma unroll
        for (int kk = 0; kk < 8; kk++) {
            uint32_t bf[8][2];
            #pragma unroll
            for (int nt = 0; nt < 8; nt++) {
                int nr = nt * 8 + groupId;   // key index within tile
                bf[nt][0] = f2tf(Ks[nr][kk * 8 + tig    ]);
                bf[nt][1] = f2tf(Ks[nr][kk * 8 + tig + 4]);
            }
            #pragma unroll
            for (int nt = 0; nt < 8; nt++)
                mma8(s[nt], qf[kk], bf[nt]);
        }

        // causal mask on diagonal tile
        if (j == qt) {
            #pragma unroll
            for (int nt = 0; nt < 8; nt++) {
                #pragma unroll
                for (int e = 0; e < 4; e++) {
                    int rq = q0 + warp * 16 + groupId + ((e >= 2) ? 8 : 0);
                    int ck = j * 64 + nt * 8 + tig * 2 + (e & 1);
                    if (ck > rq) s[nt][e] = -INFINITY;
                }
            }
        }

        // online softmax (2 rows per thread: groupId, groupId+8)
        #pragma unroll
        for (int hh = 0; hh < 2; hh++) {
            float mx = -INFINITY;
            #pragma unroll
            for (int nt = 0; nt < 8; nt++)
                mx = fmaxf(mx, fmaxf(s[nt][2 * hh], s[nt][2 * hh + 1]));
            mx = fmaxf(mx, __shfl_xor_sync(0xffffffffu, mx, 1));
            mx = fmaxf(mx, __shfl_xor_sync(0xffffffffu, mx, 2));
            float mnew = fmaxf(mrun[hh], mx);
            float corr = __expf(mrun[hh] - mnew);
            mrun[hh] = mnew;
            float sum = 0.f;
            #pragma unroll
            for (int nt = 0; nt < 8; nt++) {
                float p0 = __expf(s[nt][2 * hh]     - mnew); s[nt][2 * hh]     = p0;
                float p1 = __expf(s[nt][2 * hh + 1] - mnew); s[nt][2 * hh + 1] = p1;
                sum += p0 + p1;
            }
            sum += __shfl_xor_sync(0xffffffffu, sum, 1);
            sum += __shfl_xor_sync(0xffffffffu, sum, 2);
            lrun[hh] = lrun[hh] * corr + sum;
            #pragma unroll
            for (int nt = 0; nt < 8; nt++) {
                oacc[nt][2 * hh]     *= corr;
                oacc[nt][2 * hh + 1] *= corr;
            }
        }
        __syncthreads();  // all warps done reading Ks (K tile)

        // write P into Ks (now P tile [m][k])
        #pragma unroll
        for (int nt = 0; nt < 8; nt++) {
            #pragma unroll
            for (int e = 0; e < 4; e++) {
                int r = warp * 16 + groupId + ((e >= 2) ? 8 : 0);
                int c = nt * 8 + tig * 2 + (e & 1);
                Ks[r][c] = s[nt][e];
            }
        }
        __syncthreads();

        // O += P @ V
        #pragma unroll
        for (int kk = 0; kk < 8; kk++) {
            uint32_t pf[4];
            int mr = warp * 16 + groupId;
            pf[0] = f2tf(Ks[mr    ][kk * 8 + tig    ]);
            pf[1] = f2tf(Ks[mr + 8][kk * 8 + tig    ]);
            pf[2] = f2tf(Ks[mr    ][kk * 8 + tig + 4]);
            pf[3] = f2tf(Ks[mr + 8][kk * 8 + tig + 4]);
            uint32_t bf[8][2];
            #pragma unroll
            for (int nt = 0; nt < 8; nt++) {
                int nc = nt * 8 + groupId;   // d index
                bf[nt][0] = f2tf(Vs[kk * 8 + tig    ][nc]);
                bf[nt][1] = f2tf(Vs[kk * 8 + tig + 4][nc]);
            }
            #pragma unroll
            for (int nt = 0; nt < 8; nt++)
                mma8(oacc[nt], pf, bf[nt]);
        }
        __syncthreads();  // before next K/V load overwrites tiles
    }

    // epilogue: normalize and scatter to g_O in [B, L, D] layout
    const int b = bh / NHEADS, h = bh % NHEADS;
    float linv[2] = {1.f / lrun[0], 1.f / lrun[1]};
    #pragma unroll
    for (int nt = 0; nt < 8; nt++) {
        #pragma unroll
        for (int e = 0; e < 4; e++) {
            int hh = (e >= 2) ? 1 : 0;
            int r = q0 + warp * 16 + groupId + hh * 8;
            int d = nt * 8 + tig * 2 + (e & 1);
            g_O[((size_t)b * SEQ + r) * DMODEL + h * DHEAD + d] = oacc[nt][e] * linv[hh];
        }
    }
}

// ============================================================================
extern "C" void kernel_launch(void* const* d_in, const int* in_sizes, int n_in,
                              void* d_out, int out_size)
{
    const float* q  = (const float*)d_in[0];
    const float* k  = (const float*)d_in[1];
    const float* v  = (const float*)d_in[2];
    const float* Wq = (const float*)d_in[3];
    const float* bq = (const float*)d_in[4];
    const float* Wk = (const float*)d_in[5];
    const float* bk = (const float*)d_in[6];
    const float* Wv = (const float*)d_in[7];
    const float* bv = (const float*)d_in[8];
    const float* Wo = (const float*)d_in[9];
    const float* bo = (const float*)d_in[10];
    float* out = (float*)d_out;

    dim3 gg(DMODEL / 128, MTOT / 128);   // (8, 64)
    gemm_tf32<<<gg, 256>>>(q, Wq, bq, nullptr, 1);
    gemm_tf32<<<gg, 256>>>(k, Wk, bk, nullptr, 2);
    gemm_tf32<<<gg, 256>>>(v, Wv, bv, nullptr, 3);

    dim3 ga(SEQ / 64, BATCH * NHEADS);   // (32, 64)
    attn_kernel<<<ga, 128>>>();

    gemm_tf32<<<gg, 256>>>(nullptr, Wo, bo, out, 0);  // A = g_O
}

// round 2
// speedup vs baseline: 2.5442x; 2.5442x over previous
#include <cuda_runtime.h>
#include <cuda_fp16.h>
#include <cstdint>
#include <math.h>

#define BATCH 4
#define SEQ 2048
#define DMODEL 1024
#define NHEADS 16
#define DHEAD 64
#define MTOT (BATCH*SEQ)   // 8192

// ---------------- scratch (device globals: allocation-free) ----------------
__device__ __half g_Ah[(size_t)3*MTOT*DMODEL];     // q,k,v converted to half
__device__ __half g_Wh[(size_t)4*DMODEL*DMODEL];   // Wq,Wk,Wv,Wo converted
__device__ __half g_Qh[(size_t)MTOT*DMODEL];       // [B,H,L,Dh]
__device__ __half g_Kh[(size_t)MTOT*DMODEL];
__device__ __half g_Vh[(size_t)MTOT*DMODEL];
__device__ __half g_Oh[(size_t)MTOT*DMODEL];       // attn out [B,L,D] half

// ---------------- asm helpers ----------------
__device__ __forceinline__ void mma16(float* c, const uint32_t* a, const uint32_t* b){
    asm volatile("mma.sync.aligned.m16n8k16.row.col.f32.f16.f16.f32 "
        "{%0,%1,%2,%3}, {%4,%5,%6,%7}, {%8,%9}, {%0,%1,%2,%3};"
        : "+f"(c[0]), "+f"(c[1]), "+f"(c[2]), "+f"(c[3])
        : "r"(a[0]), "r"(a[1]), "r"(a[2]), "r"(a[3]), "r"(b[0]), "r"(b[1]));
}
__device__ __forceinline__ void ldsm4(uint32_t* r, uint32_t addr){
    asm volatile("ldmatrix.sync.aligned.m8n8.x4.shared.b16 {%0,%1,%2,%3}, [%4];"
        : "=r"(r[0]), "=r"(r[1]), "=r"(r[2]), "=r"(r[3]) : "r"(addr));
}
__device__ __forceinline__ void ldsm4t(uint32_t* r, uint32_t addr){
    asm volatile("ldmatrix.sync.aligned.m8n8.x4.trans.shared.b16 {%0,%1,%2,%3}, [%4];"
        : "=r"(r[0]), "=r"(r[1]), "=r"(r[2]), "=r"(r[3]) : "r"(addr));
}
__device__ __forceinline__ void cpa16(uint32_t dst, const void* src){
    asm volatile("cp.async.cg.shared.global [%0], [%1], 16;" :: "r"(dst), "l"(src));
}
#define CP_COMMIT()  asm volatile("cp.async.commit_group;")
#define CP_WAIT(N)   asm volatile("cp.async.wait_group %0;" :: "n"(N))
__device__ __forceinline__ float ex2f(float x){
    float y; asm("ex2.approx.f32 %0, %1;" : "=f"(y) : "f"(x)); return y;
}
__device__ __forceinline__ uint32_t packh2(float a, float b){
    __half2 h = __floats2half2_rn(a, b);
    return *reinterpret_cast<uint32_t*>(&h);
}

// ---------------- prepass: fp32 -> fp16 ----------------
__global__ void f2h_kernel(const float* __restrict__ s, __half* __restrict__ d, int n4){
    int i = blockIdx.x * blockDim.x + threadIdx.x;
    if (i < n4) {
        float4 v = reinterpret_cast<const float4*>(s)[i];
        uint2 o;
        o.x = packh2(v.x, v.y);
        o.y = packh2(v.z, v.w);
        reinterpret_cast<uint2*>(d)[i] = o;
    }
}

// ============================================================================
// GEMM: C[8192,1024] = A[8192,1024] @ W[1024,1024] + bias  (half in, fp32 acc)
// Block 128x128, 8 warps (4m x 2n), warp 32x64, BK=32, 3-stage cp.async.
// ============================================================================
#define GA_STRIDE 80     // bytes per A smem row (32+8 halves)
#define GB_STRIDE 272    // bytes per B smem row (128+8 halves)
#define GA_STAGE 10240   // 128*80
#define GB_STAGE 8704    // 32*272
#define G_STAGES 3
#define G_SMEM (G_STAGES*(GA_STAGE+GB_STAGE))   // 56832

__global__ __launch_bounds__(256) void gemm_f16(
    const __half* __restrict__ A, const __half* __restrict__ W,
    const float* __restrict__ bias, float* __restrict__ outF, int outMode)
{
    extern __shared__ __align__(16) char sm[];
    const uint32_t smBase = (uint32_t)__cvta_generic_to_shared(sm);
    const uint32_t sA0 = smBase;
    const uint32_t sB0 = smBase + G_STAGES * GA_STAGE;

    const int tid = threadIdx.x;
    const int warpId = tid >> 5, lane = tid & 31;
    const int g = lane >> 2, t = lane & 3;
    const int wm = warpId & 3, wn = warpId >> 2;
    const int m0 = blockIdx.y * 128;
    const int n0 = blockIdx.x * 128;

    // cp.async source/dst coords
    const int am = tid >> 2, akc = tid & 3;          // A: 2 rows (am, am+64), 4 chunks/row
    const int bk = tid >> 4, bnc = tid & 15;         // B: 2 rows (bk, bk+16), 16 chunks/row
    const __half* Abase = A + (size_t)(m0 + am) * DMODEL + akc * 8;
    const __half* Wbase = W + (size_t)bk * DMODEL + n0 + bnc * 8;
    const uint32_t aDst = am * GA_STRIDE + akc * 16;
    const uint32_t bDst = bk * GB_STRIDE + bnc * 16;

    // ldmatrix per-lane offsets
    const uint32_t aFragOff = (uint32_t)((wm*32 + (lane & 15)) * GA_STRIDE + (lane >> 4) * 16);
    const uint32_t bFragOff = (uint32_t)((lane & 15) * GB_STRIDE + wn*128 + (lane >> 4) * 16);

    float acc[2][8][4];
    #pragma unroll
    for (int mt = 0; mt < 2; mt++)
        #pragma unroll
        for (int nt = 0; nt < 8; nt++)
            #pragma unroll
            for (int e = 0; e < 4; e++) acc[mt][nt][e] = 0.f;

    const int KT = DMODEL / 32;  // 32 k-tiles

    // preload stages
    #pragma unroll
    for (int s = 0; s < G_STAGES; s++) {
        const __half* Asrc = Abase + s * 32;
        const __half* Wsrc = Wbase + (size_t)s * 32 * DMODEL;
        uint32_t a = sA0 + s * GA_STAGE + aDst;
        uint32_t b = sB0 + s * GB_STAGE + bDst;
        cpa16(a,                 Asrc);
        cpa16(a + 64*GA_STRIDE,  Asrc + (size_t)64 * DMODEL);
        cpa16(b,                 Wsrc);
        cpa16(b + 16*GB_STRIDE,  Wsrc + (size_t)16 * DMODEL);
        CP_COMMIT();
    }

    for (int i = 0; i < KT; i++) {
        CP_WAIT(2);
        __syncthreads();
        const int st = i % G_STAGES;
        const uint32_t aS = sA0 + st * GA_STAGE;
        const uint32_t bS = sB0 + st * GB_STAGE;

        #pragma unroll
        for (int ks = 0; ks < 32; ks += 16) {
            uint32_t af[2][4];
            #pragma unroll
            for (int mt = 0; mt < 2; mt++)
                ldsm4(af[mt], aS + aFragOff + mt * (16*GA_STRIDE) + ks * 2);
            #pragma unroll
            for (int np = 0; np < 4; np++) {
                uint32_t bf[4];
                ldsm4t(bf, bS + bFragOff + ks * GB_STRIDE + np * 32);
                #pragma unroll
                for (int mt = 0; mt < 2; mt++) {
                    mma16(acc[mt][2*np],   af[mt], bf);
                    mma16(acc[mt][2*np+1], af[mt], bf + 2);
                }
            }
        }
        __syncthreads();
        if (i + G_STAGES < KT) {
            const int kt = i + G_STAGES;
            const __half* Asrc = Abase + kt * 32;
            const __half* Wsrc = Wbase + (size_t)kt * 32 * DMODEL;
            uint32_t a = sA0 + st * GA_STAGE + aDst;
            uint32_t b = sB0 + st * GB_STAGE + bDst;
            cpa16(a,                 Asrc);
            cpa16(a + 64*GA_STRIDE,  Asrc + (size_t)64 * DMODEL);
            cpa16(b,                 Wsrc);
            cpa16(b + 16*GB_STRIDE,  Wsrc + (size_t)16 * DMODEL);
        }
        CP_COMMIT();
    }

    // epilogue
    __half* splitDst = (outMode == 1) ? g_Qh : (outMode == 2) ? g_Kh : g_Vh;
    #pragma unroll
    for (int mt = 0; mt < 2; mt++) {
        #pragma unroll
        for (int nt = 0; nt < 8; nt++) {
            int c = n0 + wn*64 + nt*8 + 2*t;
            float b0 = bias[c], b1 = bias[c+1];
            #pragma unroll
            for (int half_ = 0; half_ < 2; half_++) {
                int r = m0 + wm*32 + mt*16 + g + half_*8;
                float v0 = acc[mt][nt][2*half_]   + b0;
                float v1 = acc[mt][nt][2*half_+1] + b1;
                if (outMode == 0) {
                    float2 fv = make_float2(v0, v1);
                    *reinterpret_cast<float2*>(&outF[(size_t)r * DMODEL + c]) = fv;
                } else {
                    int b = r >> 11, l = r & (SEQ-1);
                    int h = c >> 6, d = c & (DHEAD-1);
                    size_t idx = ((((size_t)b*NHEADS + h)*SEQ) + l)*DHEAD + d;
                    uint32_t p = packh2(v0, v1);
                    *reinterpret_cast<uint32_t*>(&splitDst[idx]) = p;
                }
            }
        }
    }
}

// ============================================================================
// Flash attention (causal, fp16 mma). Grid (32, 64), 128 threads = 4 warps.
// BM=BN=64. K/V double-buffered via cp.async. P kept in registers (FA2 trick).
// ============================================================================
#define AT_STRIDE 144            // bytes per smem row (64+8 halves)
#define AT_TILE   (64*AT_STRIDE) // 9216

__global__ __launch_bounds__(128) void attn_kernel()
{
    __shared__ __align__(16) char sm[4 * AT_TILE];
    const uint32_t smBase = (uint32_t)__cvta_generic_to_shared(sm);
    const uint32_t sK0 = smBase;                 // K buf 0/1
    const uint32_t sV0 = smBase + 2*AT_TILE;     // V buf 0/1

    const int tid = threadIdx.x;
    const int warp = tid >> 5, lane = tid & 31;
    const int g = lane >> 2, t = lane & 3;
    const int bh = blockIdx.y;
    const int qt = (int)(gridDim.x - 1 - blockIdx.x);   // longest-first
    const int q0 = qt * 64;

    const __half* Qp = g_Qh + (size_t)bh * SEQ * DHEAD;
    const __half* Kp = g_Kh + (size_t)bh * SEQ * DHEAD;
    const __half* Vp = g_Vh + (size_t)bh * SEQ * DHEAD;

    // tile-copy coords: 512 chunks of 16B per 64x64 tile, 128 threads, 4 iters
    const int cr = tid >> 1;              // base pattern not used; use idx form

    // ---- stage Q into K-buf1, and K0/V0 into buf0
    {
        const __half* Qs = Qp + (size_t)q0 * DHEAD;
        #pragma unroll
        for (int p = 0; p < 4; p++) {
            int idx = tid + p*128;
            int r = idx >> 3, c = idx & 7;
            cpa16(sK0 + AT_TILE + r*AT_STRIDE + c*16, Qs + r*DHEAD + c*8);
        }
        CP_COMMIT();
        #pragma unroll
        for (int p = 0; p < 4; p++) {
            int idx = tid + p*128;
            int r = idx >> 3, c = idx & 7;
            cpa16(sK0 + r*AT_STRIDE + c*16, Kp + r*DHEAD + c*8);
            cpa16(sV0 + r*AT_STRIDE + c*16, Vp + r*DHEAD + c*8);
        }
        CP_COMMIT();
    }
    CP_WAIT(1);           // Q ready
    __syncthreads();

    // Q fragments: 4 ksteps x 4 regs
    uint32_t qf[4][4];
    {
        uint32_t qOff = sK0 + AT_TILE + (uint32_t)((warp*16 + (lane & 15)) * AT_STRIDE + (lane >> 4) * 16);
        #pragma unroll
        for (int ks = 0; ks < 4; ks++)
            ldsm4(qf[ks], qOff + ks * 32);
    }
    __syncthreads();      // Q consumed; K-buf1 free for j=1 prefetch

    // ldmatrix per-lane offsets for K (non-trans) and V (trans)
    const uint32_t kOff = (uint32_t)(((lane & 7) + ((lane >> 4) << 3)) * AT_STRIDE + ((lane >> 3) & 1) * 16);
    const uint32_t vOff = (uint32_t)((lane & 15) * AT_STRIDE + (lane >> 4) * 16);

    float oacc[8][4];
    #pragma unroll
    for (int nt = 0; nt < 8; nt++)
        #pragma unroll
        for (int e = 0; e < 4; e++) oacc[nt][e] = 0.f;
    float mrun[2] = {-INFINITY, -INFINITY};
    float lrun[2] = {0.f, 0.f};
    const float cl2e = 0.125f * 1.4426950408889634f;   // scale * log2(e)

    for (int j = 0; j <= qt; j++) {
        // prefetch j+1 into other buffer (previous compute on it is done:
        // everyone passed the barrier below at iter j-1 / Q barrier at j=0)
        if (j < qt) {
            const __half* Ks = Kp + (size_t)(j+1) * 64 * DHEAD;
            const __half* Vs = Vp + (size_t)(j+1) * 64 * DHEAD;
            uint32_t kb = sK0 + ((j+1) & 1) * AT_TILE;
            uint32_t vb = sV0 + ((j+1) & 1) * AT_TILE;
            #pragma unroll
            for (int p = 0; p < 4; p++) {
                int idx = tid + p*128;
                int r = idx >> 3, c = idx & 7;
                cpa16(kb + r*AT_STRIDE + c*16, Ks + r*DHEAD + c*8);
                cpa16(vb + r*AT_STRIDE + c*16, Vs + r*DHEAD + c*8);
            }
        }
        CP_COMMIT();
        CP_WAIT(1);        // tile j arrived
        __syncthreads();

        const uint32_t kB = sK0 + (j & 1) * AT_TILE;
        const uint32_t vB = sV0 + (j & 1) * AT_TILE;

        // ---- S = Q K^T
        float s[8][4];
        #pragma unroll
        for (int nt = 0; nt < 8; nt++)
            #pragma unroll
            for (int e = 0; e < 4; e++) s[nt][e] = 0.f;

        #pragma unroll
        for (int ks = 0; ks < 4; ks++) {
            #pragma unroll
            for (int np = 0; np < 4; np++) {
                uint32_t bf[4];
                ldsm4(bf, kB + kOff + np * (16*AT_STRIDE) + ks * 32);
                mma16(s[2*np],   qf[ks], bf);
                mma16(s[2*np+1], qf[ks], bf + 2);
            }
        }

        // ---- causal mask on diagonal tile
        if (j == qt) {
            #pragma unroll
            for (int nt = 0; nt < 8; nt++) {
                #pragma unroll
                for (int e = 0; e < 4; e++) {
                    int rq = q0 + warp*16 + g + ((e >= 2) ? 8 : 0);
                    int ck = j*64 + nt*8 + 2*t + (e & 1);
                    if (ck > rq) s[nt][e] = -INFINITY;
                }
            }
        }

        // ---- online softmax (rows g, g+8); scale folded into exp2
        #pragma unroll
        for (int hh = 0; hh < 2; hh++) {
            float mx = -INFINITY;
            #pragma unroll
            for (int nt = 0; nt < 8; nt++)
                mx = fmaxf(mx, fmaxf(s[nt][2*hh], s[nt][2*hh+1]));
            mx = fmaxf(mx, __shfl_xor_sync(0xffffffffu, mx, 1));
            mx = fmaxf(mx, __shfl_xor_sync(0xffffffffu, mx, 2));
            float mnew = fmaxf(mrun[hh], mx);
            float corr = ex2f((mrun[hh] - mnew) * cl2e);
            float mc = mnew * cl2e;
            mrun[hh] = mnew;
            float sum = 0.f;
            #pragma unroll
            for (int nt = 0; nt < 8; nt++) {
                float p0 = ex2f(fmaf(s[nt][2*hh],   cl2e, -mc)); s[nt][2*hh]   = p0;
                float p1 = ex2f(fmaf(s[nt][2*hh+1], cl2e, -mc)); s[nt][2*hh+1] = p1;
                sum += p0 + p1;
            }
            sum += __shfl_xor_sync(0xffffffffu, sum, 1);
            sum += __shfl_xor_sync(0xffffffffu, sum, 2);
            lrun[hh] = lrun[hh] * corr + sum;
            #pragma unroll
            for (int nt = 0; nt < 8; nt++) {
                oacc[nt][2*hh]   *= corr;
                oacc[nt][2*hh+1] *= corr;
            }
        }

        // ---- O += P @ V  (P direct from registers: C-layout == A-layout)
        #pragma unroll
        for (int kb = 0; kb < 4; kb++) {
            uint32_t pa[4];
            pa[0] = packh2(s[2*kb][0],   s[2*kb][1]);
            pa[1] = packh2(s[2*kb][2],   s[2*kb][3]);
            pa[2] = packh2(s[2*kb+1][0], s[2*kb+1][1]);
            pa[3] = packh2(s[2*kb+1][2], s[2*kb+1][3]);
            #pragma unroll
            for (int np = 0; np < 4; np++) {
                uint32_t bf[4];
                ldsm4t(bf, vB + vOff + kb * (16*AT_STRIDE) + np * 32);
                mma16(oacc[2*np],   pa, bf);
                mma16(oacc[2*np+1], pa, bf + 2);
            }
        }
        __syncthreads();   // all warps done with buf j before next prefetch reuses it
    }

    // ---- epilogue: normalize, half2 store into g_Oh [B, L, D]
    const int b = bh / NHEADS, h = bh % NHEADS;
    float linv[2] = {1.f / lrun[0], 1.f / lrun[1]};
    #pragma unroll
    for (int nt = 0; nt < 8; nt++) {
        #pragma unroll
        for (int hh = 0; hh < 2; hh++) {
            int r = q0 + warp*16 + g + hh*8;
            int d = nt*8 + 2*t;
            size_t idx = ((size_t)b*SEQ + r) * DMODEL + h*DHEAD + d;
            uint32_t p = packh2(oacc[nt][2*hh] * linv[hh], oacc[nt][2*hh+1] * linv[hh]);
            *reinterpret_cast<uint32_t*>(&g_Oh[idx]) = p;
        }
    }
}

// ============================================================================
extern "C" void kernel_launch(void* const* d_in, const int* in_sizes, int n_in,
                              void* d_out, int out_size)
{
    const float* q  = (const float*)d_in[0];
    const float* k  = (const float*)d_in[1];
    const float* v  = (const float*)d_in[2];
    const float* Wq = (const float*)d_in[3];
    const float* bq = (const float*)d_in[4];
    const float* Wk = (const float*)d_in[5];
    const float* bk = (const float*)d_in[6];
    const float* Wv = (const float*)d_in[7];
    const float* bv = (const float*)d_in[8];
    const float* Wo = (const float*)d_in[9];
    const float* bo = (const float*)d_in[10];
    float* out = (float*)d_out;

    __half *Ah, *Wh, *Oh;
    cudaGetSymbolAddress((void**)&Ah, g_Ah);
    cudaGetSymbolAddress((void**)&Wh, g_Wh);
    cudaGetSymbolAddress((void**)&Oh, g_Oh);

    cudaFuncSetAttribute(gemm_f16, cudaFuncAttributeMaxDynamicSharedMemorySize, G_SMEM);

    const size_t NIN = (size_t)MTOT * DMODEL;   // 8388608
    const size_t NW  = (size_t)DMODEL * DMODEL; // 1048576

    // prepass: fp32 -> fp16
    f2h_kernel<<<(int)(NIN/4/256), 256>>>(q,  Ah,          (int)(NIN/4));
    f2h_kernel<<<(int)(NIN/4/256), 256>>>(k,  Ah + NIN,    (int)(NIN/4));
    f2h_kernel<<<(int)(NIN/4/256), 256>>>(v,  Ah + 2*NIN,  (int)(NIN/4));
    f2h_kernel<<<(int)(NW/4/256),  256>>>(Wq, Wh,          (int)(NW/4));
    f2h_kernel<<<(int)(NW/4/256),  256>>>(Wk, Wh + NW,     (int)(NW/4));
    f2h_kernel<<<(int)(NW/4/256),  256>>>(Wv, Wh + 2*NW,   (int)(NW/4));
    f2h_kernel<<<(int)(NW/4/256),  256>>>(Wo, Wh + 3*NW,   (int)(NW/4));

    dim3 gg(DMODEL/128, MTOT/128);   // (8, 64)
    gemm_f16<<<gg, 256, G_SMEM>>>(Ah,         Wh,        bq, nullptr, 1);
    gemm_f16<<<gg, 256, G_SMEM>>>(Ah + NIN,   Wh + NW,   bk, nullptr, 2);
    gemm_f16<<<gg, 256, G_SMEM>>>(Ah + 2*NIN, Wh + 2*NW, bv, nullptr, 3);

    dim3 ga(SEQ/64, BATCH*NHEADS);   // (32, 64)
    attn_kernel<<<ga, 128>>>();

    gemm_f16<<<gg, 256, G_SMEM>>>(Oh, Wh + 3*NW, bo, out, 0);
}